// round 10
// baseline (speedup 1.0000x reference)
#include <cuda_runtime.h>

// WaveletSparsityLoss: 3-level Haar DWT sparsity loss on [32,1,1024,1024] fp32.
// Single-WAVE streaming kernel (grid 888 = 6 CTAs/SM x 148 SMs) so the PDL
// trigger fires at t~0 and the dependent reduce kernel's launch ramp fully
// overlaps k1. Work split: all threads do 2 compile-time-unrolled tiles; the
// first 69632 threads (272 blocks) do a statically-structured 3rd tile.
// Imbalance: 124 SMs see 14 tile-units vs 13.84 avg = 1.2%.

#define IMG          1024
#define TILES_X      128                    // 1024/8
#define TILES_PER_IMG (TILES_X * TILES_X)   // 16384
#define BATCH        32
#define TOTAL_TILES  (BATCH * TILES_PER_IMG)// 524288
#define TPB          256
#define NBLOCKS      888                    // 6 * 148: exactly one wave
#define NTHREADS     (NBLOCKS * TPB)        // 227328
#define EXTRA_TILES  (TOTAL_TILES - 2 * NTHREADS)   // 69632 threads do a 3rd tile

__device__ float g_partials[NBLOCKS];

// Thresholds (NORMALIZE=True): thr_s = (50 / 2^(level_idx-1)) / 255
// Per-coefficient scale: weight_s / (3 * N_s)
#define THR1 (50.0f / (4.0f * 255.0f))
#define THR2 (50.0f / (2.0f * 255.0f))
#define THR3 (50.0f / 255.0f)
#define C1   (1.0f / (3.0f * 3.0f * 8388608.0f))
#define C2   (1.0f / (2.0f * 3.0f * 2097152.0f))
#define C3   (1.0f / (1.0f * 3.0f * 524288.0f))

__device__ __forceinline__ float band3(float a, float b, float c, float d, float thr,
                                       float* cA) {
    float s0 = a + b, s1 = c + d;
    float d0 = a - b, d1 = c - d;
    float cH = (s0 - s1) * 0.5f;
    float cV = (d0 + d1) * 0.5f;
    float cD = (d0 - d1) * 0.5f;
    *cA = (s0 + s1) * 0.5f;
    return fminf(fabsf(cH), thr) + fminf(fabsf(cV), thr) + fminf(fabsf(cD), thr);
}

__device__ __forceinline__ float tile_loss(const float* __restrict__ pred, int tid) {
    const int b  = tid / TILES_PER_IMG;
    const int t  = tid - b * TILES_PER_IMG;
    const int ty = t / TILES_X;
    const int tx = t - ty * TILES_X;

    const float* base = pred + (size_t)b * (IMG * IMG) + (size_t)ty * 8 * IMG + (size_t)tx * 8;

    // Load the 8x8 tile as 16 independent float4 loads (high MLP).
    float x[8][8];
    #pragma unroll
    for (int row = 0; row < 8; ++row) {
        const float4 v0 = __ldg((const float4*)(base + (size_t)row * IMG));
        const float4 v1 = __ldg((const float4*)(base + (size_t)row * IMG) + 1);
        x[row][0] = v0.x; x[row][1] = v0.y; x[row][2] = v0.z; x[row][3] = v0.w;
        x[row][4] = v1.x; x[row][5] = v1.y; x[row][6] = v1.z; x[row][7] = v1.w;
    }

    // Level 1: 8x8 -> 4x4
    float A1[4][4];
    float s1 = 0.0f;
    #pragma unroll
    for (int i = 0; i < 4; ++i) {
        #pragma unroll
        for (int j = 0; j < 4; ++j) {
            s1 += band3(x[2*i][2*j], x[2*i][2*j+1], x[2*i+1][2*j], x[2*i+1][2*j+1],
                        THR1, &A1[i][j]);
        }
    }

    // Level 2: 4x4 -> 2x2
    float A2[2][2];
    float s2 = 0.0f;
    #pragma unroll
    for (int i = 0; i < 2; ++i) {
        #pragma unroll
        for (int j = 0; j < 2; ++j) {
            s2 += band3(A1[2*i][2*j], A1[2*i][2*j+1], A1[2*i+1][2*j], A1[2*i+1][2*j+1],
                        THR2, &A2[i][j]);
        }
    }

    // Level 3: 2x2 -> 1
    float cA3;
    float s3 = band3(A2[0][0], A2[0][1], A2[1][0], A2[1][1], THR3, &cA3);

    return s1 * C1 + s2 * C2 + s3 * C3;
}

__global__ void __launch_bounds__(TPB)
wavelet_tiles_kernel(const float* __restrict__ pred) {
    // Single wave: every CTA executes this immediately -> dependent kernel's
    // launch begins ~at t=0 and its ramp overlaps this whole kernel.
    asm volatile("griddepcontrol.launch_dependents;");

    const int tbase = blockIdx.x * TPB + threadIdx.x;

    // Two tiles for everyone (compile-time unrolled structure).
    float val = tile_loss(pred, tbase)
              + tile_loss(pred, tbase + NTHREADS);

    // Third tile for the first EXTRA_TILES threads (blocks 0..271 entirely).
    if (tbase < EXTRA_TILES)
        val += tile_loss(pred, tbase + 2 * NTHREADS);

    // Warp tree reduce
    #pragma unroll
    for (int off = 16; off > 0; off >>= 1)
        val += __shfl_xor_sync(0xffffffffu, val, off);

    __shared__ float warp_sums[TPB / 32];
    const int lane = threadIdx.x & 31;
    const int wid  = threadIdx.x >> 5;
    if (lane == 0) warp_sums[wid] = val;
    __syncthreads();

    if (threadIdx.x == 0) {
        float s = 0.0f;
        #pragma unroll
        for (int w = 0; w < TPB / 32; ++w) s += warp_sums[w];
        g_partials[blockIdx.x] = s;
    }
}

__global__ void __launch_bounds__(TPB)
reduce_final_kernel(float* __restrict__ out) {
    // Launched early via PDL; block until producer grid completes (memory
    // visibility included).
    asm volatile("griddepcontrol.wait;");

    // 888 partials, 256 threads -> up to 4 each, deterministic fixed order.
    double acc = 0.0;
    #pragma unroll
    for (int i = 0; i < (NBLOCKS + TPB - 1) / TPB; ++i) {   // 4 iterations
        const int idx = threadIdx.x + i * TPB;
        if (idx < NBLOCKS) acc += (double)g_partials[idx];
    }

    // Warp-level double reduction.
    #pragma unroll
    for (int off = 16; off > 0; off >>= 1)
        acc += __shfl_xor_sync(0xffffffffu, acc, off);

    __shared__ double wsum[TPB / 32];                  // 8 warps
    const int lane = threadIdx.x & 31;
    const int wid  = threadIdx.x >> 5;
    if (lane == 0) wsum[wid] = acc;
    __syncthreads();

    if (wid == 0) {
        double v = (lane < TPB / 32) ? wsum[lane] : 0.0;
        #pragma unroll
        for (int off = 4; off > 0; off >>= 1)
            v += __shfl_xor_sync(0xffffffffu, v, off);
        if (lane == 0) out[0] = (float)v;
    }
}

extern "C" void kernel_launch(void* const* d_in, const int* in_sizes, int n_in,
                              void* d_out, int out_size) {
    const float* pred = (const float*)d_in[0];
    float* out = (float*)d_out;

    wavelet_tiles_kernel<<<NBLOCKS, TPB>>>(pred);

    // Dependent launch: overlaps k1 (waits inside via griddepcontrol.wait).
    cudaLaunchConfig_t cfg = {};
    cfg.gridDim  = dim3(1, 1, 1);
    cfg.blockDim = dim3(TPB, 1, 1);
    cfg.dynamicSmemBytes = 0;
    cfg.stream = 0;
    cudaLaunchAttribute attrs[1];
    attrs[0].id = cudaLaunchAttributeProgrammaticStreamSerialization;
    attrs[0].val.programmaticStreamSerializationAllowed = 1;
    cfg.attrs = attrs;
    cfg.numAttrs = 1;
    cudaLaunchKernelEx(&cfg, reduce_final_kernel, out);
}

// round 11
// speedup vs baseline: 1.0935x; 1.0935x over previous
#include <cuda_runtime.h>

// WaveletSparsityLoss: 3-level Haar DWT sparsity loss on [32,1,1024,1024] fp32.
// R1's streaming kernel (fastest measured: 2048 blocks, 1 tile/thread, fully
// unrolled 16x LDG.128) with the grid reduction done by a fire-and-forget
// RED.ADD.F32 of each block's partial into d_out[0]. No second kernel, no
// ticket, no wait: the reduction adds ~5 cycles to each block's exit path.
// d_out is zero-initialized by a tiny async memset node in the graph.

#define IMG          1024
#define TILES_X      128                    // 1024/8
#define TILES_PER_IMG (TILES_X * TILES_X)   // 16384
#define BATCH        32
#define TOTAL_TILES  (BATCH * TILES_PER_IMG)// 524288
#define TPB          256
#define NBLOCKS      (TOTAL_TILES / TPB)    // 2048 (exact)

// Thresholds (NORMALIZE=True): thr_s = (50 / 2^(level_idx-1)) / 255
// Per-coefficient scale: weight_s / (3 * N_s)
#define THR1 (50.0f / (4.0f * 255.0f))
#define THR2 (50.0f / (2.0f * 255.0f))
#define THR3 (50.0f / 255.0f)
#define C1   (1.0f / (3.0f * 3.0f * 8388608.0f))
#define C2   (1.0f / (2.0f * 3.0f * 2097152.0f))
#define C3   (1.0f / (1.0f * 3.0f * 524288.0f))

__device__ __forceinline__ float band3(float a, float b, float c, float d, float thr,
                                       float* cA) {
    float s0 = a + b, s1 = c + d;
    float d0 = a - b, d1 = c - d;
    float cH = (s0 - s1) * 0.5f;
    float cV = (d0 + d1) * 0.5f;
    float cD = (d0 - d1) * 0.5f;
    *cA = (s0 + s1) * 0.5f;
    return fminf(fabsf(cH), thr) + fminf(fabsf(cV), thr) + fminf(fabsf(cD), thr);
}

__global__ void __launch_bounds__(TPB)
wavelet_tiles_kernel(const float* __restrict__ pred, float* __restrict__ out) {
    const int tid = blockIdx.x * TPB + threadIdx.x;   // global tile id, exact fit
    const int b  = tid / TILES_PER_IMG;
    const int t  = tid - b * TILES_PER_IMG;
    const int ty = t / TILES_X;
    const int tx = t - ty * TILES_X;

    const float* base = pred + (size_t)b * (IMG * IMG) + (size_t)ty * 8 * IMG + (size_t)tx * 8;

    // Load the 8x8 tile as 16 independent float4 loads (high MLP).
    float x[8][8];
    #pragma unroll
    for (int row = 0; row < 8; ++row) {
        const float4 v0 = __ldg((const float4*)(base + (size_t)row * IMG));
        const float4 v1 = __ldg((const float4*)(base + (size_t)row * IMG) + 1);
        x[row][0] = v0.x; x[row][1] = v0.y; x[row][2] = v0.z; x[row][3] = v0.w;
        x[row][4] = v1.x; x[row][5] = v1.y; x[row][6] = v1.z; x[row][7] = v1.w;
    }

    // Level 1: 8x8 -> 4x4
    float A1[4][4];
    float s1 = 0.0f;
    #pragma unroll
    for (int i = 0; i < 4; ++i) {
        #pragma unroll
        for (int j = 0; j < 4; ++j) {
            s1 += band3(x[2*i][2*j], x[2*i][2*j+1], x[2*i+1][2*j], x[2*i+1][2*j+1],
                        THR1, &A1[i][j]);
        }
    }

    // Level 2: 4x4 -> 2x2
    float A2[2][2];
    float s2 = 0.0f;
    #pragma unroll
    for (int i = 0; i < 2; ++i) {
        #pragma unroll
        for (int j = 0; j < 2; ++j) {
            s2 += band3(A1[2*i][2*j], A1[2*i][2*j+1], A1[2*i+1][2*j], A1[2*i+1][2*j+1],
                        THR2, &A2[i][j]);
        }
    }

    // Level 3: 2x2 -> 1
    float cA3;
    float s3 = band3(A2[0][0], A2[0][1], A2[1][0], A2[1][1], THR3, &cA3);

    float val = s1 * C1 + s2 * C2 + s3 * C3;

    // Warp tree reduce (fixed order, deterministic within block).
    #pragma unroll
    for (int off = 16; off > 0; off >>= 1)
        val += __shfl_xor_sync(0xffffffffu, val, off);

    __shared__ float warp_sums[TPB / 32];
    const int lane = threadIdx.x & 31;
    const int wid  = threadIdx.x >> 5;
    if (lane == 0) warp_sums[wid] = val;
    __syncthreads();

    if (threadIdx.x == 0) {
        float s = 0.0f;
        #pragma unroll
        for (int w = 0; w < TPB / 32; ++w) s += warp_sums[w];
        // Fire-and-forget reduction into the output scalar (RED.ADD.F32:
        // no return, no scoreboard wait, ~free on the block exit path).
        atomicAdd(out, s);
    }
}

extern "C" void kernel_launch(void* const* d_in, const int* in_sizes, int n_in,
                              void* d_out, int out_size) {
    const float* pred = (const float*)d_in[0];
    float* out = (float*)d_out;
    // d_out is poisoned by the harness; zero the 4-byte accumulator first.
    cudaMemsetAsync(out, 0, sizeof(float));
    wavelet_tiles_kernel<<<NBLOCKS, TPB>>>(pred, out);
}

// round 12
// speedup vs baseline: 1.1136x; 1.0183x over previous
#include <cuda_runtime.h>

// WaveletSparsityLoss: 3-level Haar DWT sparsity loss on [32,1,1024,1024] fp32.
// Paired-thread streaming: two threads split each 8x8 tile into 8x4 halves so
// every warp-wide LDG.128 covers a dense 512B span (4 full 128B wavefronts,
// vs 8 half-used ones in the 1-thread/tile version). Levels 1-2 are thread-
// local; level 3 needs a single shfl_xor pair exchange. Grid reduction is a
// fire-and-forget RED.ADD.F32 into d_out[0] (zeroed by an async memset node).

#define IMG          1024
#define TILES_X      128                    // 1024/8
#define TILES_PER_IMG (TILES_X * TILES_X)   // 16384
#define BATCH        32
#define TOTAL_TILES  (BATCH * TILES_PER_IMG)// 524288
#define TPB          256
#define NBLOCKS      (2 * TOTAL_TILES / TPB) // 4096 (2 threads per tile)

// Thresholds (NORMALIZE=True): thr_s = (50 / 2^(level_idx-1)) / 255
// Per-coefficient scale: weight_s / (3 * N_s)
#define THR1 (50.0f / (4.0f * 255.0f))
#define THR2 (50.0f / (2.0f * 255.0f))
#define THR3 (50.0f / 255.0f)
#define C1   (1.0f / (3.0f * 3.0f * 8388608.0f))
#define C2   (1.0f / (2.0f * 3.0f * 2097152.0f))
#define C3   (1.0f / (1.0f * 3.0f * 524288.0f))

__device__ __forceinline__ float band3(float a, float b, float c, float d, float thr,
                                       float* cA) {
    float s0 = a + b, s1 = c + d;
    float d0 = a - b, d1 = c - d;
    float cH = (s0 - s1) * 0.5f;
    float cV = (d0 + d1) * 0.5f;
    float cD = (d0 - d1) * 0.5f;
    *cA = (s0 + s1) * 0.5f;
    return fminf(fabsf(cH), thr) + fminf(fabsf(cV), thr) + fminf(fabsf(cD), thr);
}

__global__ void __launch_bounds__(TPB)
wavelet_tiles_kernel(const float* __restrict__ pred, float* __restrict__ out) {
    const int gtid = blockIdx.x * TPB + threadIdx.x;
    const int tile = gtid >> 1;               // tile id (2 threads per tile)
    const int half = gtid & 1;                // 0 = cols 0-3, 1 = cols 4-7

    const int b  = tile / TILES_PER_IMG;
    const int t  = tile - b * TILES_PER_IMG;
    const int ty = t / TILES_X;
    const int tx = t - ty * TILES_X;

    const float* base = pred + (size_t)b * (IMG * IMG)
                             + (size_t)ty * 8 * IMG + (size_t)tx * 8 + half * 4;

    // 8 rows x 4 cols: one dense float4 per row. Warp-wide: lane addresses
    // are 16B-strided -> each LDG.128 covers a contiguous 512B span.
    float x[8][4];
    #pragma unroll
    for (int row = 0; row < 8; ++row) {
        const float4 v = __ldg((const float4*)(base + (size_t)row * IMG));
        x[row][0] = v.x; x[row][1] = v.y; x[row][2] = v.z; x[row][3] = v.w;
    }

    // Level 1: 8x4 half-tile -> 4x2 cA block (8 of the tile's 16 quads).
    float A1[4][2];
    float s1 = 0.0f;
    #pragma unroll
    for (int i = 0; i < 4; ++i) {
        #pragma unroll
        for (int j = 0; j < 2; ++j) {
            s1 += band3(x[2*i][2*j], x[2*i][2*j+1], x[2*i+1][2*j], x[2*i+1][2*j+1],
                        THR1, &A1[i][j]);
        }
    }

    // Level 2: this thread's A1 columns are the tile's global columns
    // {2*half, 2*half+1}, so the level-2 quad at column j2=half is entirely
    // thread-local. Two quads (rows 0,1), no exchange needed.
    float A2loc[2];   // = global A2[i2][half]
    float s2 = 0.0f;
    #pragma unroll
    for (int i = 0; i < 2; ++i) {
        s2 += band3(A1[2*i][0], A1[2*i][1], A1[2*i+1][0], A1[2*i+1][1],
                    THR2, &A2loc[i]);
    }

    // Level 3: exchange the pair's A2 column via shfl. band3's loss terms are
    // invariant under (a<->b, c<->d) swap, so both threads compute the same
    // s3 and each contributes half.
    const float p0 = __shfl_xor_sync(0xffffffffu, A2loc[0], 1);
    const float p1 = __shfl_xor_sync(0xffffffffu, A2loc[1], 1);
    float cA3;
    const float s3 = band3(A2loc[0], p0, A2loc[1], p1, THR3, &cA3);

    float val = s1 * C1 + s2 * C2 + s3 * (0.5f * C3);

    // Warp tree reduce (fixed order, deterministic within block).
    #pragma unroll
    for (int off = 16; off > 0; off >>= 1)
        val += __shfl_xor_sync(0xffffffffu, val, off);

    __shared__ float warp_sums[TPB / 32];
    const int lane = threadIdx.x & 31;
    const int wid  = threadIdx.x >> 5;
    if (lane == 0) warp_sums[wid] = val;
    __syncthreads();

    if (threadIdx.x == 0) {
        float s = 0.0f;
        #pragma unroll
        for (int w = 0; w < TPB / 32; ++w) s += warp_sums[w];
        // Fire-and-forget reduction into the output scalar (RED.ADD.F32:
        // no return, no scoreboard wait, ~free on the block exit path).
        atomicAdd(out, s);
    }
}

extern "C" void kernel_launch(void* const* d_in, const int* in_sizes, int n_in,
                              void* d_out, int out_size) {
    const float* pred = (const float*)d_in[0];
    float* out = (float*)d_out;
    // d_out is poisoned by the harness; zero the 4-byte accumulator first.
    cudaMemsetAsync(out, 0, sizeof(float));
    wavelet_tiles_kernel<<<NBLOCKS, TPB>>>(pred, out);
}